// round 15
// baseline (speedup 1.0000x reference)
#include <cuda_runtime.h>
#include <cuda_fp16.h>
#include <cstdint>

typedef uint32_t u32;

// Fixed dims: 65536 rows, Dn=128, L=256, H=8, DH=32. Only graph branch matters
// (reference loop overwrites `out`; graph branch has T=1 -> rank-1 kv).
#define NROWS_TOTAL 65536
#define ROWS_PER_BLK 64
#define THREADS 256
#define NBLKS (NROWS_TOTAL / ROWS_PER_BLK)   // 1024

// ---------------- SMEM layout (bytes) --------------------------------------
// f[0..3327] floats (13312B): [0..255] bnq | [256..511] kvec | [512..767] b_out
//                             [768..2815] U[8][256] | [2816..3327] c[64][8]
// X @13312 (17408B fp16 [64][136])   Q @30720 (33792B fp16 [64][264])
// WC @64512: 2 x 20480B chunk buffers ([256][40] half, K=32 each)
#define OFF_X    13312
#define OFF_Q    30720
#define OFF_WC   64512
#define WCBUF    20480
#define SMEM_BYTES 105472   // 2 CTAs/SM
#define FI_C 2816

#define XSTR 68     // u32 words/row (272 B)  68%32=4  -> LDSM conflict-free
#define QSTR 132    // (528 B) 132%32=4 ; chunk rows 80B=20 words ✓

// ---------------- device globals (precomputed each launch) -----------------
__device__ float  g_p4part[4 * 128 * 256];     // K-split partials of W_node@Wq
__device__ __half g_Wch[12 * 256 * 40];        // 12 K=32 chunks: 0-3 Wnq^T, 4-11 Wout^T
__device__ __half g_X16[NROWS_TOTAL * 136];    // X pre-converted fp16, padded rows
__device__ float g_bnq[256], g_kvec[256], g_U[2048];
__device__ float g_kraw[256], g_vraw[256];

// ---------------- helpers ---------------------------------------------------
__device__ __forceinline__ void mma16816(float* d, const u32* a, const u32* b) {
    asm volatile(
        "mma.sync.aligned.m16n8k16.row.col.f32.f16.f16.f32 "
        "{%0,%1,%2,%3}, {%4,%5,%6,%7}, {%8,%9}, {%0,%1,%2,%3};"
        : "+f"(d[0]), "+f"(d[1]), "+f"(d[2]), "+f"(d[3])
        : "r"(a[0]), "r"(a[1]), "r"(a[2]), "r"(a[3]), "r"(b[0]), "r"(b[1]));
}
__device__ __forceinline__ void ldsm4(u32* r, u32 addr) {
    asm volatile("ldmatrix.sync.aligned.m8n8.x4.shared.b16 {%0,%1,%2,%3}, [%4];"
        : "=r"(r[0]), "=r"(r[1]), "=r"(r[2]), "=r"(r[3]) : "r"(addr));
}
__device__ __forceinline__ u32 packh2(float x, float y) {
    __half2 h = __floats2half2_rn(x, y);
    return *reinterpret_cast<u32*>(&h);
}
#define CP16(dst, src) \
    asm volatile("cp.async.cg.shared.global [%0], [%1], 16;" :: "r"(dst), "l"(src))
#define CP_COMMIT() asm volatile("cp.async.commit_group;" ::: "memory")
#define CP_WAIT0()  asm volatile("cp.async.wait_group 0;" ::: "memory")

// ---------------- precompute A: p2 + p4 + p5 + pX merged -------------------
// bid 0..95     p2: lifted-graph + three K=256 GEMVs (warp per output)
// bid 96..607   p4: K-split partials of W_node@Wq
// bid 608..863  p5: W_out -> fp16 chunk layout (chunks 4..11)
// bid 864..2911 pX: node_features fp32 -> padded fp16 rows
__global__ void pA_kernel(const float* __restrict__ energy,
                          const float* __restrict__ W_graph,
                          const float* __restrict__ b_graph,
                          const float* __restrict__ Wk, const float* __restrict__ bk,
                          const float* __restrict__ Wv, const float* __restrict__ bv,
                          const float* __restrict__ Wq, const float* __restrict__ bq,
                          const float* __restrict__ b_node,
                          const float* __restrict__ W_node,
                          const float* __restrict__ W_out,
                          const float* __restrict__ X)
{
    __shared__ float sh[256];
    const int bid = blockIdx.x;
    const int t = threadIdx.x;

    if (bid < 96) {
        const int warp = t >> 5, lane = t & 31;
        const int oid = bid * 8 + warp;
        const int kind = oid >> 8;
        const int j = oid & 255;
        {
            float acc = b_graph[t];
            #pragma unroll
            for (int d = 0; d < 32; d++) acc += energy[d] * W_graph[d * 256 + t];
            sh[t] = acc;
        }
        __syncthreads();
        const float* W; const float* xv; float bias;
        if (kind == 0)      { W = Wk + 2 * 65536; xv = sh;     bias = bk[512 + j]; }
        else if (kind == 1) { W = Wv + 2 * 65536; xv = sh;     bias = bv[512 + j]; }
        else                { W = Wq;             xv = b_node; bias = bq[j]; }
        float s = 0.0f;
        #pragma unroll
        for (int u = 0; u < 8; u++) { int i = lane + 32 * u; s += xv[i] * W[i * 256 + j]; }
        #pragma unroll
        for (int o = 16; o > 0; o >>= 1) s += __shfl_xor_sync(0xffffffffu, s, o);
        if (lane == 0) {
            s += bias;
            if (kind == 0) g_kraw[j] = s;
            else if (kind == 1) g_vraw[j] = s;
            else g_bnq[j] = s;
        }
    } else if (bid < 608) {
        const int idx = bid - 96;
        const int i = idx & 127, kc = idx >> 7;
        if (t < 64) sh[t] = W_node[i * 256 + kc * 64 + t];
        __syncthreads();
        const float* Wqp = Wq + (kc * 64) * 256 + t;
        float a[8];
        #pragma unroll
        for (int q = 0; q < 8; q++) a[q] = 0.0f;
        #pragma unroll
        for (int m = 0; m < 64; m += 8) {
            #pragma unroll
            for (int q = 0; q < 8; q++)
                a[q] = fmaf(sh[m + q], Wqp[(m + q) * 256], a[q]);
        }
        float r = ((a[0] + a[1]) + (a[2] + a[3])) + ((a[4] + a[5]) + (a[6] + a[7]));
        g_p4part[(kc * 128 + i) * 256 + t] = r;
    } else if (bid < 864) {
        // p5: W_out row m -> chunk (4 + m/32), position m%32, n = t
        const int m = bid - 608;
        g_Wch[(4 + (m >> 5)) * 10240 + t * 40 + (m & 31)] =
            __float2half(W_out[m * 256 + t]);
    } else {
        // pX: 32 rows per block -> padded fp16
        const int b = bid - 864;                   // 0..2047
        const float2* xs = (const float2*)(X + (size_t)b * 32 * 128);
        u32* xd = (u32*)g_X16 + (size_t)b * 32 * 68;
        #pragma unroll
        for (int i = 0; i < 8; i++) {
            const int idx = i * 256 + t;           // < 2048
            const int r = idx >> 6, cp = idx & 63;
            float2 v = xs[idx];
            xd[r * 68 + cp] = packh2(v.x, v.y);
        }
    }
}

// ---------------- precompute B: p3 + p6 merged -----------------------------
__global__ void pB_kernel(const float* __restrict__ W_out)
{
    const int bid = blockIdx.x;
    const int t = threadIdx.x;
    if (bid == 0) {
        const int w = t >> 5, lane = t & 31;
        float x = g_kraw[w * 32 + lane];
        float m = x;
        #pragma unroll
        for (int o = 16; o > 0; o >>= 1) m = fmaxf(m, __shfl_xor_sync(0xffffffffu, m, o));
        const float e = __expf(x - m);
        float s = e;
        #pragma unroll
        for (int o = 16; o > 0; o >>= 1) s += __shfl_xor_sync(0xffffffffu, s, o);
        g_kvec[w * 32 + lane] = e / s;
    } else if (bid < 9) {
        const int h = bid - 1;
        __shared__ float sv[32];
        if (t < 32) sv[t] = g_vraw[h * 32 + t];
        __syncthreads();
        float u = 0.0f;
        #pragma unroll
        for (int e2 = 0; e2 < 32; e2++) u += sv[e2] * W_out[(h * 32 + e2) * 256 + t];
        g_U[h * 256 + t] = u;
    } else {
        // p6: reduce partials -> Wnq chunk layout (chunks 0..3)
        const int j = (bid - 9) * 2 + (t >> 7);
        const int i = t & 127;
        float s = g_p4part[i * 256 + j] + g_p4part[(128 + i) * 256 + j]
                + g_p4part[(256 + i) * 256 + j] + g_p4part[(384 + i) * 256 + j];
        g_Wch[(i >> 5) * 10240 + j * 40 + (i & 31)] = __float2half(s);
    }
}

// ---------------- main HMMA kernel (256 thr, 64 rows, 2 CTA/SM) ------------
extern __shared__ char s_raw[];

__device__ __forceinline__ void prefetch_chunk(u32 sb, int ck, int tid) {
    const u32 dst = sb + OFF_WC + (u32)(ck & 1) * WCBUF;
    const char* src = (const char*)g_Wch + (size_t)ck * 20480;
    #pragma unroll
    for (int i = 0; i < 5; i++) {
        const int idx = tid + i * 256;            // < 1280
        CP16(dst + (u32)(idx * 16), src + idx * 16);
    }
    CP_COMMIT();
}

__global__ __launch_bounds__(THREADS, 2)
void ghca_main_kernel(const float* __restrict__ b_out,
                      float* __restrict__ out)
{
    float* f = (float*)s_raw;
    const u32 sb = (u32)__cvta_generic_to_shared(s_raw);
    const int tid = threadIdx.x;
    const int wid = tid >> 5, lane = tid & 31;
    const int g = lane >> 2, tig = lane & 3;
    const int wr = wid & 1, wc = wid >> 1;     // warp: rows wr*32.., cols wc*64..
    const int row0 = blockIdx.x * ROWS_PER_BLK;

    const int tile = lane >> 3, tr8 = lane & 7;
    const u32 aXbase = sb + OFF_X +
        (u32)((wr * 32 + ((tile & 1) << 3) + tr8) * 272 + ((tile >> 1) << 4));
    const u32 aQbase = sb + OFF_Q +
        (u32)((wr * 32 + ((tile & 1) << 3) + tr8) * 528 + ((tile >> 1) << 4));
    const u32 bWrel =
        (u32)((wc * 64 + ((tile >> 1) << 3) + tr8) * 80 + ((tile & 1) << 4));

    // ---- issue X tile copy (flat, pre-converted): 64 rows = 1088 x 16B ----
    {
        const char* src = (const char*)g_X16 + (size_t)row0 * 272;
        const u32 dst = sb + OFF_X;
        #pragma unroll
        for (int i = 0; i < 4; i++) {
            const int idx = tid + i * 256;
            CP16(dst + (u32)(idx * 16), src + idx * 16);
        }
        if (tid < 64) {
            const int idx = 1024 + tid;
            CP16(dst + (u32)(idx * 16), src + idx * 16);
        }
        CP_COMMIT();
    }
    // ---- chunk 0 ----
    prefetch_chunk(sb, 0, tid);

    // ---- stage small arrays (plain loads; covered by first barrier) ----
    for (int t = tid; t < 256; t += THREADS) {
        f[t]       = g_bnq[t];
        f[256 + t] = g_kvec[t];
        f[512 + t] = b_out[t];
    }
    for (int t = tid; t < 2048; t += THREADS) f[768 + t] = g_U[t];

    float d[2][8][4];
    #pragma unroll
    for (int mt = 0; mt < 2; mt++)
        #pragma unroll
        for (int nt = 0; nt < 8; nt++)
            #pragma unroll
            for (int c = 0; c < 4; c++) d[mt][nt][c] = 0.0f;

    // ---- unified stream: 12 K=32 chunks (0-3: phase1, 4-11: phase2) ----
    #pragma unroll 1
    for (int ck = 0; ck < 12; ck++) {
        CP_WAIT0();        // chunk ck (and, at ck=0, X) resident
        __syncthreads();
        if (ck < 11) prefetch_chunk(sb, ck + 1, tid);

        const bool ph1 = (ck < 4);
        const u32 abase = ph1 ? (aXbase + (u32)(ck * 64))
                              : (aQbase + (u32)((ck - 4) * 64));
        const u32 astr = ph1 ? 272u : 528u;
        const u32 bbase = sb + OFF_WC + (u32)(ck & 1) * WCBUF + bWrel;

        #pragma unroll
        for (int ks = 0; ks < 2; ks++) {
            u32 a0[4], a1[4];
            ldsm4(a0, abase + (u32)(ks * 32));
            ldsm4(a1, abase + 16 * astr + (u32)(ks * 32));
            #pragma unroll
            for (int p = 0; p < 4; p++) {
                u32 b[4];
                ldsm4(b, bbase + (u32)(p * 1280) + (u32)(ks * 32));
                mma16816(d[0][2 * p],     a0, b);
                mma16816(d[0][2 * p + 1], a0, b + 2);
                mma16816(d[1][2 * p],     a1, b);
                mma16816(d[1][2 * p + 1], a1, b + 2);
            }
        }

        if (ck == 3) {
            // ---- softmax (inputs unit-scale; no max pass), build c, Q ----
            // prefetch(4) already in flight above -> overlaps this block
            u32* Qh = (u32*)(s_raw + OFF_Q);
            float* fc = f + FI_C;
            #pragma unroll
            for (int mt = 0; mt < 2; mt++) {
                #pragma unroll
                for (int rh = 0; rh < 2; rh++) {
                    const int row = wr * 32 + mt * 16 + rh * 8 + g;
                    #pragma unroll
                    for (int hg = 0; hg < 2; hg++) {
                        const int head = wc * 2 + hg;
                        float y[8];
                        float s = 0.0f;
                        #pragma unroll
                        for (int q = 0; q < 4; q++) {
                            const int col = wc * 64 + (hg * 4 + q) * 8 + tig * 2;
                            y[q * 2]     = __expf(d[mt][hg * 4 + q][rh * 2]     + f[col]);
                            y[q * 2 + 1] = __expf(d[mt][hg * 4 + q][rh * 2 + 1] + f[col + 1]);
                            s += y[q * 2] + y[q * 2 + 1];
                        }
                        s += __shfl_xor_sync(0xffffffffu, s, 1);
                        s += __shfl_xor_sync(0xffffffffu, s, 2);
                        const float inv = 1.0f / s;
                        float pd = 0.0f;
                        #pragma unroll
                        for (int q = 0; q < 4; q++) {
                            const int col = wc * 64 + (hg * 4 + q) * 8 + tig * 2;
                            y[q * 2]     *= inv;
                            y[q * 2 + 1] *= inv;
                            pd += y[q * 2] * f[256 + col] + y[q * 2 + 1] * f[256 + col + 1];
                        }
                        pd += __shfl_xor_sync(0xffffffffu, pd, 1);
                        pd += __shfl_xor_sync(0xffffffffu, pd, 2);
                        if (tig == 0)
                            fc[row * 8 + head] = (pd >= 1e-8f) ? 1.0f : pd * 1e8f;
                        #pragma unroll
                        for (int q = 0; q < 4; q++) {
                            const int wi = row * QSTR + wc * 32 + (hg * 4 + q) * 4 + tig;
                            Qh[wi] = packh2(y[q * 2], y[q * 2 + 1]);
                        }
                    }
                }
            }
            // reset accumulators for phase 2
            #pragma unroll
            for (int mt = 0; mt < 2; mt++)
                #pragma unroll
                for (int nt = 0; nt < 8; nt++)
                    #pragma unroll
                    for (int c = 0; c < 4; c++) d[mt][nt][c] = 0.0f;
            // Q-write visibility handled by the barrier at top of ck=4
        }
    }

    // ---- epilogue: + b_out + c @ U, direct float2 stores ----
    {
        const float* fc = f + FI_C;
        #pragma unroll
        for (int mt = 0; mt < 2; mt++) {
            const int r0 = wr * 32 + mt * 16 + g;
            const int r1 = r0 + 8;
            float cc0[8], cc1[8];
            #pragma unroll
            for (int h = 0; h < 8; h++) { cc0[h] = fc[r0 * 8 + h]; cc1[h] = fc[r1 * 8 + h]; }
            #pragma unroll
            for (int nt = 0; nt < 8; nt++) {
                const int col = wc * 64 + nt * 8 + tig * 2;
                const float2 bo = *(const float2*)(f + 512 + col);
                float v00 = d[mt][nt][0] + bo.x;
                float v01 = d[mt][nt][1] + bo.y;
                float v10 = d[mt][nt][2] + bo.x;
                float v11 = d[mt][nt][3] + bo.y;
                #pragma unroll
                for (int h = 0; h < 8; h++) {
                    const float2 u2 = *(const float2*)(f + 768 + h * 256 + col);
                    v00 = fmaf(cc0[h], u2.x, v00);
                    v01 = fmaf(cc0[h], u2.y, v01);
                    v10 = fmaf(cc1[h], u2.x, v10);
                    v11 = fmaf(cc1[h], u2.y, v11);
                }
                float2* o0 = (float2*)(out + (size_t)(row0 + r0) * 256 + col);
                float2* o1 = (float2*)(out + (size_t)(row0 + r1) * 256 + col);
                *o0 = make_float2(v00, v01);
                *o1 = make_float2(v10, v11);
            }
        }
    }
}

// ---------------- launch ----------------------------------------------------
extern "C" void kernel_launch(void* const* d_in, const int* in_sizes, int n_in,
                              void* d_out, int out_size)
{
    const float* node    = (const float*)d_in[0];
    const float* energy  = (const float*)d_in[2];
    const float* W_node  = (const float*)d_in[3];
    const float* b_node  = (const float*)d_in[4];
    const float* W_graph = (const float*)d_in[7];
    const float* b_graph = (const float*)d_in[8];
    const float* Wq      = (const float*)d_in[9];
    const float* bq      = (const float*)d_in[10];
    const float* Wk      = (const float*)d_in[11];
    const float* bk      = (const float*)d_in[12];
    const float* Wv      = (const float*)d_in[13];
    const float* bv      = (const float*)d_in[14];
    const float* W_out   = (const float*)d_in[15];
    const float* b_out   = (const float*)d_in[16];
    float* out = (float*)d_out;

    pA_kernel<<<2912, 256>>>(energy, W_graph, b_graph, Wk, bk, Wv, bv,
                             Wq, bq, b_node, W_node, W_out, node);
    pB_kernel<<<137, 256>>>(W_out);

    cudaFuncSetAttribute(ghca_main_kernel,
                         cudaFuncAttributeMaxDynamicSharedMemorySize, SMEM_BYTES);
    ghca_main_kernel<<<NBLKS, THREADS, SMEM_BYTES>>>(b_out, out);
}

// round 16
// speedup vs baseline: 1.4948x; 1.4948x over previous
#include <cuda_runtime.h>
#include <cuda_fp16.h>
#include <cstdint>

typedef uint32_t u32;

// Fixed dims: 65536 rows, Dn=128, L=256, H=8, DH=32. Only graph branch matters
// (reference loop overwrites `out`; graph branch has T=1 -> rank-1 kv).
#define NROWS_TOTAL 65536
#define ROWS_PER_BLK 64
#define THREADS 256
#define NBLKS (NROWS_TOTAL / ROWS_PER_BLK)   // 1024

// ---------------- SMEM layout (bytes) --------------------------------------
// f[0..3327] floats (13312B): [0..255] bnq | [256..511] kvec | [512..767] b_out
//                             [768..2815] U[8][256] | [2816..3327] c[64][8]
// X @13312 (17408B fp16 [64][136])   Q @30720 (33792B fp16 [64][264])
//   (Q region doubles as fp32 X staging (32768B) before phase 1)
// WC @64512: 2 x 20480B chunk buffers ([256][40] half, K=32 each)
#define OFF_X    13312
#define OFF_Q    30720
#define OFF_WC   64512
#define WCBUF    20480
#define SMEM_BYTES 105472   // 2 CTAs/SM
#define FI_C 2816

#define XSTR 68     // u32 words/row (272 B)  68%32=4  -> LDSM conflict-free
#define QSTR 132    // (528 B) 132%32=4 ; chunk rows 80B=20 words ✓

// ---------------- device globals (precomputed each launch) -----------------
__device__ float  g_p4part[4 * 128 * 256];     // K-split partials of W_node@Wq
__device__ __half g_Wch[12 * 256 * 40];        // 12 K=32 chunks: 0-3 Wnq^T, 4-11 Wout^T
__device__ float g_bnq[256], g_kvec[256], g_U[2048];
__device__ float g_kraw[256], g_vraw[256];

// ---------------- helpers ---------------------------------------------------
__device__ __forceinline__ void mma16816(float* d, const u32* a, const u32* b) {
    asm volatile(
        "mma.sync.aligned.m16n8k16.row.col.f32.f16.f16.f32 "
        "{%0,%1,%2,%3}, {%4,%5,%6,%7}, {%8,%9}, {%0,%1,%2,%3};"
        : "+f"(d[0]), "+f"(d[1]), "+f"(d[2]), "+f"(d[3])
        : "r"(a[0]), "r"(a[1]), "r"(a[2]), "r"(a[3]), "r"(b[0]), "r"(b[1]));
}
__device__ __forceinline__ void ldsm4(u32* r, u32 addr) {
    asm volatile("ldmatrix.sync.aligned.m8n8.x4.shared.b16 {%0,%1,%2,%3}, [%4];"
        : "=r"(r[0]), "=r"(r[1]), "=r"(r[2]), "=r"(r[3]) : "r"(addr));
}
__device__ __forceinline__ u32 packh2(float x, float y) {
    __half2 h = __floats2half2_rn(x, y);
    return *reinterpret_cast<u32*>(&h);
}
#define CP16(dst, src) \
    asm volatile("cp.async.cg.shared.global [%0], [%1], 16;" :: "r"(dst), "l"(src))
#define CP_COMMIT() asm volatile("cp.async.commit_group;" ::: "memory")
#define CP_WAIT0()  asm volatile("cp.async.wait_group 0;" ::: "memory")

// ---------------- precompute A: p2 + p4 + p5 merged (no pX anymore) --------
// bid 0..95     p2: lifted-graph + three K=256 GEMVs (warp per output)
// bid 96..607   p4: K-split partials of W_node@Wq
// bid 608..863  p5: W_out -> fp16 chunk layout (chunks 4..11)
__global__ void pA_kernel(const float* __restrict__ energy,
                          const float* __restrict__ W_graph,
                          const float* __restrict__ b_graph,
                          const float* __restrict__ Wk, const float* __restrict__ bk,
                          const float* __restrict__ Wv, const float* __restrict__ bv,
                          const float* __restrict__ Wq, const float* __restrict__ bq,
                          const float* __restrict__ b_node,
                          const float* __restrict__ W_node,
                          const float* __restrict__ W_out)
{
    __shared__ float sh[256];
    const int bid = blockIdx.x;
    const int t = threadIdx.x;

    if (bid < 96) {
        const int warp = t >> 5, lane = t & 31;
        const int oid = bid * 8 + warp;
        const int kind = oid >> 8;
        const int j = oid & 255;
        {
            float acc = b_graph[t];
            #pragma unroll
            for (int d = 0; d < 32; d++) acc += energy[d] * W_graph[d * 256 + t];
            sh[t] = acc;
        }
        __syncthreads();
        const float* W; const float* xv; float bias;
        if (kind == 0)      { W = Wk + 2 * 65536; xv = sh;     bias = bk[512 + j]; }
        else if (kind == 1) { W = Wv + 2 * 65536; xv = sh;     bias = bv[512 + j]; }
        else                { W = Wq;             xv = b_node; bias = bq[j]; }
        float s = 0.0f;
        #pragma unroll
        for (int u = 0; u < 8; u++) { int i = lane + 32 * u; s += xv[i] * W[i * 256 + j]; }
        #pragma unroll
        for (int o = 16; o > 0; o >>= 1) s += __shfl_xor_sync(0xffffffffu, s, o);
        if (lane == 0) {
            s += bias;
            if (kind == 0) g_kraw[j] = s;
            else if (kind == 1) g_vraw[j] = s;
            else g_bnq[j] = s;
        }
    } else if (bid < 608) {
        const int idx = bid - 96;
        const int i = idx & 127, kc = idx >> 7;
        if (t < 64) sh[t] = W_node[i * 256 + kc * 64 + t];
        __syncthreads();
        const float* Wqp = Wq + (kc * 64) * 256 + t;
        float a[8];
        #pragma unroll
        for (int q = 0; q < 8; q++) a[q] = 0.0f;
        #pragma unroll
        for (int m = 0; m < 64; m += 8) {
            #pragma unroll
            for (int q = 0; q < 8; q++)
                a[q] = fmaf(sh[m + q], Wqp[(m + q) * 256], a[q]);
        }
        float r = ((a[0] + a[1]) + (a[2] + a[3])) + ((a[4] + a[5]) + (a[6] + a[7]));
        g_p4part[(kc * 128 + i) * 256 + t] = r;
    } else {
        // p5: W_out row m -> chunk (4 + m/32), position m%32, n = t
        const int m = bid - 608;
        g_Wch[(4 + (m >> 5)) * 10240 + t * 40 + (m & 31)] =
            __float2half(W_out[m * 256 + t]);
    }
}

// ---------------- precompute B: p3 + p6 merged -----------------------------
__global__ void pB_kernel(const float* __restrict__ W_out)
{
    const int bid = blockIdx.x;
    const int t = threadIdx.x;
    if (bid == 0) {
        const int w = t >> 5, lane = t & 31;
        float x = g_kraw[w * 32 + lane];
        float m = x;
        #pragma unroll
        for (int o = 16; o > 0; o >>= 1) m = fmaxf(m, __shfl_xor_sync(0xffffffffu, m, o));
        const float e = __expf(x - m);
        float s = e;
        #pragma unroll
        for (int o = 16; o > 0; o >>= 1) s += __shfl_xor_sync(0xffffffffu, s, o);
        g_kvec[w * 32 + lane] = e / s;
    } else if (bid < 9) {
        const int h = bid - 1;
        __shared__ float sv[32];
        if (t < 32) sv[t] = g_vraw[h * 32 + t];
        __syncthreads();
        float u = 0.0f;
        #pragma unroll
        for (int e2 = 0; e2 < 32; e2++) u += sv[e2] * W_out[(h * 32 + e2) * 256 + t];
        g_U[h * 256 + t] = u;
    } else {
        // p6: reduce partials -> Wnq chunk layout (chunks 0..3)
        const int j = (bid - 9) * 2 + (t >> 7);
        const int i = t & 127;
        float s = g_p4part[i * 256 + j] + g_p4part[(128 + i) * 256 + j]
                + g_p4part[(256 + i) * 256 + j] + g_p4part[(384 + i) * 256 + j];
        g_Wch[(i >> 5) * 10240 + j * 40 + (i & 31)] = __float2half(s);
    }
}

// ---------------- main HMMA kernel (256 thr, 64 rows, 2 CTA/SM) ------------
extern __shared__ char s_raw[];

__device__ __forceinline__ void prefetch_chunk(u32 sb, int ck, int tid) {
    const u32 dst = sb + OFF_WC + (u32)(ck & 1) * WCBUF;
    const char* src = (const char*)g_Wch + (size_t)ck * 20480;
    #pragma unroll
    for (int i = 0; i < 5; i++) {
        const int idx = tid + i * 256;            // < 1280
        CP16(dst + (u32)(idx * 16), src + idx * 16);
    }
    CP_COMMIT();
}

__global__ __launch_bounds__(THREADS, 2)
void ghca_main_kernel(const float* __restrict__ X,
                      const float* __restrict__ b_out,
                      float* __restrict__ out)
{
    float* f = (float*)s_raw;
    const u32 sb = (u32)__cvta_generic_to_shared(s_raw);
    const int tid = threadIdx.x;
    const int wid = tid >> 5, lane = tid & 31;
    const int g = lane >> 2, tig = lane & 3;
    const int wr = wid & 1, wc = wid >> 1;     // warp: rows wr*32.., cols wc*64..
    const int row0 = blockIdx.x * ROWS_PER_BLK;

    const int tile = lane >> 3, tr8 = lane & 7;
    const u32 aXbase = sb + OFF_X +
        (u32)((wr * 32 + ((tile & 1) << 3) + tr8) * 272 + ((tile >> 1) << 4));
    const u32 aQbase = sb + OFF_Q +
        (u32)((wr * 32 + ((tile & 1) << 3) + tr8) * 528 + ((tile >> 1) << 4));
    const u32 bWrel =
        (u32)((wc * 64 + ((tile >> 1) << 3) + tr8) * 80 + ((tile & 1) << 4));

    // ---- issue fp32 X tile copy into Q region (staging): 2048 x 16B ----
    {
        const char* src = (const char*)(X + (size_t)row0 * 128);
        const u32 dst = sb + OFF_Q;
        #pragma unroll
        for (int i = 0; i < 8; i++) {
            const int idx = tid + i * 256;        // < 2048
            CP16(dst + (u32)(idx * 16), src + idx * 16);
        }
        CP_COMMIT();
    }
    // ---- chunk 0 ----
    prefetch_chunk(sb, 0, tid);

    // ---- stage small arrays (plain loads; covered by first barrier) ----
    for (int t = tid; t < 256; t += THREADS) {
        f[t]       = g_bnq[t];
        f[256 + t] = g_kvec[t];
        f[512 + t] = b_out[t];
    }
    for (int t = tid; t < 2048; t += THREADS) f[768 + t] = g_U[t];

    // ---- wait X fp32 + chunk0; convert X to padded fp16 at OFF_X ----
    CP_WAIT0();
    __syncthreads();
    {
        const float2* xs = (const float2*)(s_raw + OFF_Q);
        u32* xd = (u32*)(s_raw + OFF_X);
        #pragma unroll
        for (int i = 0; i < 16; i++) {
            const int idx = tid + i * 256;        // < 4096 float2
            const int r = idx >> 6, cp = idx & 63;
            float2 v = xs[idx];
            xd[r * XSTR + cp] = packh2(v.x, v.y);
        }
    }

    float d[2][8][4];
    #pragma unroll
    for (int mt = 0; mt < 2; mt++)
        #pragma unroll
        for (int nt = 0; nt < 8; nt++)
            #pragma unroll
            for (int c = 0; c < 4; c++) d[mt][nt][c] = 0.0f;

    // ---- unified stream: 12 K=32 chunks (0-3: phase1, 4-11: phase2) ----
    #pragma unroll 1
    for (int ck = 0; ck < 12; ck++) {
        CP_WAIT0();        // chunk ck resident (ck=0: already drained above)
        __syncthreads();   // at ck=0 also publishes the X fp16 conversion
        if (ck < 11) prefetch_chunk(sb, ck + 1, tid);

        const bool ph1 = (ck < 4);
        const u32 abase = ph1 ? (aXbase + (u32)(ck * 64))
                              : (aQbase + (u32)((ck - 4) * 64));
        const u32 astr = ph1 ? 272u : 528u;
        const u32 bbase = sb + OFF_WC + (u32)(ck & 1) * WCBUF + bWrel;

        #pragma unroll
        for (int ks = 0; ks < 2; ks++) {
            u32 a0[4], a1[4];
            ldsm4(a0, abase + (u32)(ks * 32));
            ldsm4(a1, abase + 16 * astr + (u32)(ks * 32));
            #pragma unroll
            for (int p = 0; p < 4; p++) {
                u32 b[4];
                ldsm4(b, bbase + (u32)(p * 1280) + (u32)(ks * 32));
                mma16816(d[0][2 * p],     a0, b);
                mma16816(d[0][2 * p + 1], a0, b + 2);
                mma16816(d[1][2 * p],     a1, b);
                mma16816(d[1][2 * p + 1], a1, b + 2);
            }
        }

        if (ck == 3) {
            // ---- softmax (inputs unit-scale; no max pass), build c, Q ----
            // prefetch(4) already in flight above -> overlaps this block
            u32* Qh = (u32*)(s_raw + OFF_Q);
            float* fc = f + FI_C;
            #pragma unroll
            for (int mt = 0; mt < 2; mt++) {
                #pragma unroll
                for (int rh = 0; rh < 2; rh++) {
                    const int row = wr * 32 + mt * 16 + rh * 8 + g;
                    #pragma unroll
                    for (int hg = 0; hg < 2; hg++) {
                        const int head = wc * 2 + hg;
                        float y[8];
                        float s = 0.0f;
                        #pragma unroll
                        for (int q = 0; q < 4; q++) {
                            const int col = wc * 64 + (hg * 4 + q) * 8 + tig * 2;
                            y[q * 2]     = __expf(d[mt][hg * 4 + q][rh * 2]     + f[col]);
                            y[q * 2 + 1] = __expf(d[mt][hg * 4 + q][rh * 2 + 1] + f[col + 1]);
                            s += y[q * 2] + y[q * 2 + 1];
                        }
                        s += __shfl_xor_sync(0xffffffffu, s, 1);
                        s += __shfl_xor_sync(0xffffffffu, s, 2);
                        const float inv = 1.0f / s;
                        float pd = 0.0f;
                        #pragma unroll
                        for (int q = 0; q < 4; q++) {
                            const int col = wc * 64 + (hg * 4 + q) * 8 + tig * 2;
                            y[q * 2]     *= inv;
                            y[q * 2 + 1] *= inv;
                            pd += y[q * 2] * f[256 + col] + y[q * 2 + 1] * f[256 + col + 1];
                        }
                        pd += __shfl_xor_sync(0xffffffffu, pd, 1);
                        pd += __shfl_xor_sync(0xffffffffu, pd, 2);
                        if (tig == 0)
                            fc[row * 8 + head] = (pd >= 1e-8f) ? 1.0f : pd * 1e8f;
                        #pragma unroll
                        for (int q = 0; q < 4; q++) {
                            const int wi = row * QSTR + wc * 32 + (hg * 4 + q) * 4 + tig;
                            Qh[wi] = packh2(y[q * 2], y[q * 2 + 1]);
                        }
                    }
                }
            }
            // reset accumulators for phase 2
            #pragma unroll
            for (int mt = 0; mt < 2; mt++)
                #pragma unroll
                for (int nt = 0; nt < 8; nt++)
                    #pragma unroll
                    for (int c = 0; c < 4; c++) d[mt][nt][c] = 0.0f;
            // Q-write visibility handled by the barrier at top of ck=4
        }
    }

    // ---- epilogue: + b_out + c @ U, direct float2 stores ----
    {
        const float* fc = f + FI_C;
        #pragma unroll
        for (int mt = 0; mt < 2; mt++) {
            const int r0 = wr * 32 + mt * 16 + g;
            const int r1 = r0 + 8;
            float cc0[8], cc1[8];
            #pragma unroll
            for (int h = 0; h < 8; h++) { cc0[h] = fc[r0 * 8 + h]; cc1[h] = fc[r1 * 8 + h]; }
            #pragma unroll
            for (int nt = 0; nt < 8; nt++) {
                const int col = wc * 64 + nt * 8 + tig * 2;
                const float2 bo = *(const float2*)(f + 512 + col);
                float v00 = d[mt][nt][0] + bo.x;
                float v01 = d[mt][nt][1] + bo.y;
                float v10 = d[mt][nt][2] + bo.x;
                float v11 = d[mt][nt][3] + bo.y;
                #pragma unroll
                for (int h = 0; h < 8; h++) {
                    const float2 u2 = *(const float2*)(f + 768 + h * 256 + col);
                    v00 = fmaf(cc0[h], u2.x, v00);
                    v01 = fmaf(cc0[h], u2.y, v01);
                    v10 = fmaf(cc1[h], u2.x, v10);
                    v11 = fmaf(cc1[h], u2.y, v11);
                }
                float2* o0 = (float2*)(out + (size_t)(row0 + r0) * 256 + col);
                float2* o1 = (float2*)(out + (size_t)(row0 + r1) * 256 + col);
                *o0 = make_float2(v00, v01);
                *o1 = make_float2(v10, v11);
            }
        }
    }
}

// ---------------- launch ----------------------------------------------------
extern "C" void kernel_launch(void* const* d_in, const int* in_sizes, int n_in,
                              void* d_out, int out_size)
{
    const float* node    = (const float*)d_in[0];
    const float* energy  = (const float*)d_in[2];
    const float* W_node  = (const float*)d_in[3];
    const float* b_node  = (const float*)d_in[4];
    const float* W_graph = (const float*)d_in[7];
    const float* b_graph = (const float*)d_in[8];
    const float* Wq      = (const float*)d_in[9];
    const float* bq      = (const float*)d_in[10];
    const float* Wk      = (const float*)d_in[11];
    const float* bk      = (const float*)d_in[12];
    const float* Wv      = (const float*)d_in[13];
    const float* bv      = (const float*)d_in[14];
    const float* W_out   = (const float*)d_in[15];
    const float* b_out   = (const float*)d_in[16];
    float* out = (float*)d_out;

    pA_kernel<<<864, 256>>>(energy, W_graph, b_graph, Wk, bk, Wv, bv,
                            Wq, bq, b_node, W_node, W_out);
    pB_kernel<<<137, 256>>>(W_out);

    cudaFuncSetAttribute(ghca_main_kernel,
                         cudaFuncAttributeMaxDynamicSharedMemorySize, SMEM_BYTES);
    ghca_main_kernel<<<NBLKS, THREADS, SMEM_BYTES>>>(node, b_out, out);
}

// round 17
// speedup vs baseline: 1.5883x; 1.0625x over previous
#include <cuda_runtime.h>
#include <cuda_fp16.h>
#include <cstdint>

typedef uint32_t u32;

// Fixed dims: 65536 rows, Dn=128, L=256, H=8, DH=32. Only graph branch matters
// (reference loop overwrites `out`; graph branch has T=1 -> rank-1 kv).
#define NROWS_TOTAL 65536
#define ROWS_PER_BLK 64
#define THREADS 256
#define NBLKS (NROWS_TOTAL / ROWS_PER_BLK)   // 1024

// ---------------- SMEM layout (bytes) --------------------------------------
// f[0..3327] floats (13312B): [0..255] bnq | [256..511] kvec | [512..767] b_out
//                             [768..2815] U[8][256] | [2816..3327] c[64][8]
// X @13312 (17408B fp16 [64][136])   Q @30720 (33792B fp16 [64][264])
//   (Q region doubles as fp32 X staging (32768B) before phase 1)
// WC @64512: 2 x 20480B chunk buffers ([256][40] half, K=32 each)
#define OFF_X    13312
#define OFF_Q    30720
#define OFF_WC   64512
#define WCBUF    20480
#define SMEM_BYTES 105472   // 2 CTAs/SM
#define FI_C 2816

#define XSTR 68     // u32 words/row (272 B)  68%32=4  -> LDSM conflict-free
#define QSTR 132    // (528 B) 132%32=4 ; chunk rows 80B=20 words ✓

// ---------------- device globals (precomputed each launch) -----------------
__device__ float  g_p4part[8 * 128 * 256];     // K-split partials of W_node@Wq
__device__ __half g_Wch[12 * 256 * 40];        // 12 K=32 chunks: 0-3 Wnq^T, 4-11 Wout^T
__device__ float g_bnq[256], g_kvec[256], g_U[2048];
__device__ float g_kraw[256], g_vraw[256];

// ---------------- helpers ---------------------------------------------------
__device__ __forceinline__ void mma16816(float* d, const u32* a, const u32* b) {
    asm volatile(
        "mma.sync.aligned.m16n8k16.row.col.f32.f16.f16.f32 "
        "{%0,%1,%2,%3}, {%4,%5,%6,%7}, {%8,%9}, {%0,%1,%2,%3};"
        : "+f"(d[0]), "+f"(d[1]), "+f"(d[2]), "+f"(d[3])
        : "r"(a[0]), "r"(a[1]), "r"(a[2]), "r"(a[3]), "r"(b[0]), "r"(b[1]));
}
__device__ __forceinline__ void ldsm4(u32* r, u32 addr) {
    asm volatile("ldmatrix.sync.aligned.m8n8.x4.shared.b16 {%0,%1,%2,%3}, [%4];"
        : "=r"(r[0]), "=r"(r[1]), "=r"(r[2]), "=r"(r[3]) : "r"(addr));
}
__device__ __forceinline__ u32 packh2(float x, float y) {
    __half2 h = __floats2half2_rn(x, y);
    return *reinterpret_cast<u32*>(&h);
}
#define CP16(dst, src) \
    asm volatile("cp.async.cg.shared.global [%0], [%1], 16;" :: "r"(dst), "l"(src))
#define CP_COMMIT() asm volatile("cp.async.commit_group;" ::: "memory")
#define CP_WAIT0()  asm volatile("cp.async.wait_group 0;" ::: "memory")

// ---------------- precompute A: p2 + p4 + p5 merged ------------------------
// bid 0..95      p2: lifted-graph + three K=256 GEMVs (warp per output)
// bid 96..1119   p4: K-split partials of W_node@Wq (8 chunks of K=32)
// bid 1120..1375 p5: W_out -> fp16 chunk layout (chunks 4..11)
__global__ void pA_kernel(const float* __restrict__ energy,
                          const float* __restrict__ W_graph,
                          const float* __restrict__ b_graph,
                          const float* __restrict__ Wk, const float* __restrict__ bk,
                          const float* __restrict__ Wv, const float* __restrict__ bv,
                          const float* __restrict__ Wq, const float* __restrict__ bq,
                          const float* __restrict__ b_node,
                          const float* __restrict__ W_node,
                          const float* __restrict__ W_out)
{
    __shared__ float sh[256];
    const int bid = blockIdx.x;
    const int t = threadIdx.x;

    if (bid < 96) {
        const int warp = t >> 5, lane = t & 31;
        const int oid = bid * 8 + warp;
        const int kind = oid >> 8;
        const int j = oid & 255;
        {
            float acc = b_graph[t];
            #pragma unroll
            for (int d = 0; d < 32; d++) acc += energy[d] * W_graph[d * 256 + t];
            sh[t] = acc;
        }
        __syncthreads();
        const float* W; const float* xv; float bias;
        if (kind == 0)      { W = Wk + 2 * 65536; xv = sh;     bias = bk[512 + j]; }
        else if (kind == 1) { W = Wv + 2 * 65536; xv = sh;     bias = bv[512 + j]; }
        else                { W = Wq;             xv = b_node; bias = bq[j]; }
        float s = 0.0f;
        #pragma unroll
        for (int u = 0; u < 8; u++) { int i = lane + 32 * u; s += xv[i] * W[i * 256 + j]; }
        #pragma unroll
        for (int o = 16; o > 0; o >>= 1) s += __shfl_xor_sync(0xffffffffu, s, o);
        if (lane == 0) {
            s += bias;
            if (kind == 0) g_kraw[j] = s;
            else if (kind == 1) g_vraw[j] = s;
            else g_bnq[j] = s;
        }
    } else if (bid < 1120) {
        // p4: K=32 chunk kc of row i of Wnq = W_node @ Wq
        const int idx = bid - 96;
        const int i = idx & 127, kc = idx >> 7;     // kc 0..7
        if (t < 32) sh[t] = W_node[i * 256 + kc * 32 + t];
        __syncthreads();
        const float* Wqp = Wq + (kc * 32) * 256 + t;
        float a[8];
        #pragma unroll
        for (int q = 0; q < 8; q++) a[q] = 0.0f;
        #pragma unroll
        for (int m = 0; m < 32; m += 8) {
            #pragma unroll
            for (int q = 0; q < 8; q++)
                a[q] = fmaf(sh[m + q], Wqp[(m + q) * 256], a[q]);
        }
        float r = ((a[0] + a[1]) + (a[2] + a[3])) + ((a[4] + a[5]) + (a[6] + a[7]));
        g_p4part[(kc * 128 + i) * 256 + t] = r;
    } else {
        // p5: W_out row m -> chunk (4 + m/32), position m%32, n = t
        const int m = bid - 1120;
        g_Wch[(4 + (m >> 5)) * 10240 + t * 40 + (m & 31)] =
            __float2half(W_out[m * 256 + t]);
    }
}

// ---------------- precompute B: p3 + p6 merged -----------------------------
__global__ void pB_kernel(const float* __restrict__ W_out)
{
    const int bid = blockIdx.x;
    const int t = threadIdx.x;
    if (bid == 0) {
        const int w = t >> 5, lane = t & 31;
        float x = g_kraw[w * 32 + lane];
        float m = x;
        #pragma unroll
        for (int o = 16; o > 0; o >>= 1) m = fmaxf(m, __shfl_xor_sync(0xffffffffu, m, o));
        const float e = __expf(x - m);
        float s = e;
        #pragma unroll
        for (int o = 16; o > 0; o >>= 1) s += __shfl_xor_sync(0xffffffffu, s, o);
        g_kvec[w * 32 + lane] = e / s;
    } else if (bid < 9) {
        const int h = bid - 1;
        __shared__ float sv[32];
        if (t < 32) sv[t] = g_vraw[h * 32 + t];
        __syncthreads();
        float u = 0.0f;
        #pragma unroll
        for (int e2 = 0; e2 < 32; e2++) u += sv[e2] * W_out[(h * 32 + e2) * 256 + t];
        g_U[h * 256 + t] = u;
    } else {
        // p6: reduce 8 partials -> Wnq chunk layout (chunks 0..3)
        const int j = (bid - 9) * 2 + (t >> 7);
        const int i = t & 127;
        float s = 0.0f;
        #pragma unroll
        for (int kc = 0; kc < 8; kc++)
            s += g_p4part[(kc * 128 + i) * 256 + j];
        g_Wch[(i >> 5) * 10240 + j * 40 + (i & 31)] = __float2half(s);
    }
}

// ---------------- main HMMA kernel (256 thr, 64 rows, 2 CTA/SM) ------------
extern __shared__ char s_raw[];

__device__ __forceinline__ void prefetch_chunk(u32 sb, int ck, int tid) {
    const u32 dst = sb + OFF_WC + (u32)(ck & 1) * WCBUF;
    const char* src = (const char*)g_Wch + (size_t)ck * 20480;
    #pragma unroll
    for (int i = 0; i < 5; i++) {
        const int idx = tid + i * 256;            // < 1280
        CP16(dst + (u32)(idx * 16), src + idx * 16);
    }
    CP_COMMIT();
}

__global__ __launch_bounds__(THREADS, 2)
void ghca_main_kernel(const float* __restrict__ X,
                      const float* __restrict__ b_out,
                      float* __restrict__ out)
{
    float* f = (float*)s_raw;
    const u32 sb = (u32)__cvta_generic_to_shared(s_raw);
    const int tid = threadIdx.x;
    const int wid = tid >> 5, lane = tid & 31;
    const int g = lane >> 2, tig = lane & 3;
    const int wr = wid & 1, wc = wid >> 1;     // warp: rows wr*32.., cols wc*64..
    const int row0 = blockIdx.x * ROWS_PER_BLK;

    const int tile = lane >> 3, tr8 = lane & 7;
    const u32 aXbase = sb + OFF_X +
        (u32)((wr * 32 + ((tile & 1) << 3) + tr8) * 272 + ((tile >> 1) << 4));
    const u32 aQbase = sb + OFF_Q +
        (u32)((wr * 32 + ((tile & 1) << 3) + tr8) * 528 + ((tile >> 1) << 4));
    const u32 bWrel =
        (u32)((wc * 64 + ((tile >> 1) << 3) + tr8) * 80 + ((tile & 1) << 4));

    // ---- issue fp32 X tile copy into Q region (staging): 2048 x 16B ----
    {
        const char* src = (const char*)(X + (size_t)row0 * 128);
        const u32 dst = sb + OFF_Q;
        #pragma unroll
        for (int i = 0; i < 8; i++) {
            const int idx = tid + i * 256;        // < 2048
            CP16(dst + (u32)(idx * 16), src + idx * 16);
        }
        // small arrays via cp.async too: U (512x16B) + bnq/kvec/b_out (64 each)
        #pragma unroll
        for (int i = 0; i < 2; i++) {
            const int idx = tid + i * 256;        // < 512
            CP16(sb + (u32)(768 * 4 + idx * 16), (const char*)g_U + idx * 16);
        }
        if (tid < 64) {
            CP16(sb + (u32)(tid * 16),             (const char*)g_bnq + tid * 16);
            CP16(sb + (u32)(256 * 4 + tid * 16),   (const char*)g_kvec + tid * 16);
            CP16(sb + (u32)(512 * 4 + tid * 16),   (const char*)b_out + tid * 16);
        }
        CP_COMMIT();
    }
    // ---- chunk 0 ----
    prefetch_chunk(sb, 0, tid);

    // ---- wait X fp32 + smalls + chunk0; convert X to padded fp16 ----
    CP_WAIT0();
    __syncthreads();
    {
        const float2* xs = (const float2*)(s_raw + OFF_Q);
        u32* xd = (u32*)(s_raw + OFF_X);
        #pragma unroll
        for (int i = 0; i < 16; i++) {
            const int idx = tid + i * 256;        // < 4096 float2
            const int r = idx >> 6, cp = idx & 63;
            float2 v = xs[idx];
            xd[r * XSTR + cp] = packh2(v.x, v.y);
        }
    }

    float d[2][8][4];
    #pragma unroll
    for (int mt = 0; mt < 2; mt++)
        #pragma unroll
        for (int nt = 0; nt < 8; nt++)
            #pragma unroll
            for (int c = 0; c < 4; c++) d[mt][nt][c] = 0.0f;

    // ---- unified stream: 12 K=32 chunks (0-3: phase1, 4-11: phase2) ----
    #pragma unroll 1
    for (int ck = 0; ck < 12; ck++) {
        CP_WAIT0();        // chunk ck resident (ck=0: already drained above)
        __syncthreads();   // at ck=0 also publishes the X fp16 conversion
        if (ck < 11) prefetch_chunk(sb, ck + 1, tid);

        const bool ph1 = (ck < 4);
        const u32 abase = ph1 ? (aXbase + (u32)(ck * 64))
                              : (aQbase + (u32)((ck - 4) * 64));
        const u32 astr = ph1 ? 272u : 528u;
        const u32 bbase = sb + OFF_WC + (u32)(ck & 1) * WCBUF + bWrel;

        #pragma unroll
        for (int ks = 0; ks < 2; ks++) {
            u32 a0[4], a1[4];
            ldsm4(a0, abase + (u32)(ks * 32));
            ldsm4(a1, abase + 16 * astr + (u32)(ks * 32));
            #pragma unroll
            for (int p = 0; p < 4; p++) {
                u32 b[4];
                ldsm4(b, bbase + (u32)(p * 1280) + (u32)(ks * 32));
                mma16816(d[0][2 * p],     a0, b);
                mma16816(d[0][2 * p + 1], a0, b + 2);
                mma16816(d[1][2 * p],     a1, b);
                mma16816(d[1][2 * p + 1], a1, b + 2);
            }
        }

        if (ck == 3) {
            // ---- softmax (inputs unit-scale; no max pass), build c, Q ----
            // prefetch(4) already in flight above -> overlaps this block
            u32* Qh = (u32*)(s_raw + OFF_Q);
            float* fc = f + FI_C;
            #pragma unroll
            for (int mt = 0; mt < 2; mt++) {
                #pragma unroll
                for (int rh = 0; rh < 2; rh++) {
                    const int row = wr * 32 + mt * 16 + rh * 8 + g;
                    #pragma unroll
                    for (int hg = 0; hg < 2; hg++) {
                        const int head = wc * 2 + hg;
                        float y[8];
                        float s = 0.0f;
                        #pragma unroll
                        for (int q = 0; q < 4; q++) {
                            const int col = wc * 64 + (hg * 4 + q) * 8 + tig * 2;
                            y[q * 2]     = __expf(d[mt][hg * 4 + q][rh * 2]     + f[col]);
                            y[q * 2 + 1] = __expf(d[mt][hg * 4 + q][rh * 2 + 1] + f[col + 1]);
                            s += y[q * 2] + y[q * 2 + 1];
                        }
                        s += __shfl_xor_sync(0xffffffffu, s, 1);
                        s += __shfl_xor_sync(0xffffffffu, s, 2);
                        const float inv = 1.0f / s;
                        float pd = 0.0f;
                        #pragma unroll
                        for (int q = 0; q < 4; q++) {
                            const int col = wc * 64 + (hg * 4 + q) * 8 + tig * 2;
                            y[q * 2]     *= inv;
                            y[q * 2 + 1] *= inv;
                            pd += y[q * 2] * f[256 + col] + y[q * 2 + 1] * f[256 + col + 1];
                        }
                        pd += __shfl_xor_sync(0xffffffffu, pd, 1);
                        pd += __shfl_xor_sync(0xffffffffu, pd, 2);
                        if (tig == 0)
                            fc[row * 8 + head] = (pd >= 1e-8f) ? 1.0f : pd * 1e8f;
                        #pragma unroll
                        for (int q = 0; q < 4; q++) {
                            const int wi = row * QSTR + wc * 32 + (hg * 4 + q) * 4 + tig;
                            Qh[wi] = packh2(y[q * 2], y[q * 2 + 1]);
                        }
                    }
                }
            }
            // reset accumulators for phase 2
            #pragma unroll
            for (int mt = 0; mt < 2; mt++)
                #pragma unroll
                for (int nt = 0; nt < 8; nt++)
                    #pragma unroll
                    for (int c = 0; c < 4; c++) d[mt][nt][c] = 0.0f;
            // Q-write visibility handled by the barrier at top of ck=4
        }
    }

    // ---- epilogue: + b_out + c @ U, direct float2 stores ----
    {
        const float* fc = f + FI_C;
        #pragma unroll
        for (int mt = 0; mt < 2; mt++) {
            const int r0 = wr * 32 + mt * 16 + g;
            const int r1 = r0 + 8;
            float cc0[8], cc1[8];
            #pragma unroll
            for (int h = 0; h < 8; h++) { cc0[h] = fc[r0 * 8 + h]; cc1[h] = fc[r1 * 8 + h]; }
            #pragma unroll
            for (int nt = 0; nt < 8; nt++) {
                const int col = wc * 64 + nt * 8 + tig * 2;
                const float2 bo = *(const float2*)(f + 512 + col);
                float v00 = d[mt][nt][0] + bo.x;
                float v01 = d[mt][nt][1] + bo.y;
                float v10 = d[mt][nt][2] + bo.x;
                float v11 = d[mt][nt][3] + bo.y;
                #pragma unroll
                for (int h = 0; h < 8; h++) {
                    const float2 u2 = *(const float2*)(f + 768 + h * 256 + col);
                    v00 = fmaf(cc0[h], u2.x, v00);
                    v01 = fmaf(cc0[h], u2.y, v01);
                    v10 = fmaf(cc1[h], u2.x, v10);
                    v11 = fmaf(cc1[h], u2.y, v11);
                }
                float2* o0 = (float2*)(out + (size_t)(row0 + r0) * 256 + col);
                float2* o1 = (float2*)(out + (size_t)(row0 + r1) * 256 + col);
                *o0 = make_float2(v00, v01);
                *o1 = make_float2(v10, v11);
            }
        }
    }
}

// ---------------- launch ----------------------------------------------------
extern "C" void kernel_launch(void* const* d_in, const int* in_sizes, int n_in,
                              void* d_out, int out_size)
{
    const float* node    = (const float*)d_in[0];
    const float* energy  = (const float*)d_in[2];
    const float* W_node  = (const float*)d_in[3];
    const float* b_node  = (const float*)d_in[4];
    const float* W_graph = (const float*)d_in[7];
    const float* b_graph = (const float*)d_in[8];
    const float* Wq      = (const float*)d_in[9];
    const float* bq      = (const float*)d_in[10];
    const float* Wk      = (const float*)d_in[11];
    const float* bk      = (const float*)d_in[12];
    const float* Wv      = (const float*)d_in[13];
    const float* bv      = (const float*)d_in[14];
    const float* W_out   = (const float*)d_in[15];
    const float* b_out   = (const float*)d_in[16];
    float* out = (float*)d_out;

    pA_kernel<<<1376, 256>>>(energy, W_graph, b_graph, Wk, bk, Wv, bv,
                             Wq, bq, b_node, W_node, W_out);
    pB_kernel<<<137, 256>>>(W_out);

    cudaFuncSetAttribute(ghca_main_kernel,
                         cudaFuncAttributeMaxDynamicSharedMemorySize, SMEM_BYTES);
    ghca_main_kernel<<<NBLKS, THREADS, SMEM_BYTES>>>(node, b_out, out);
}